// round 9
// baseline (speedup 1.0000x reference)
#include <cuda_runtime.h>
#include <cuda_bf16.h>

#define TT   65536
#define BB   4
#define W    16
#define NL   18
#define TILE 512
#define NTH  256
#define HOFF 1856

typedef unsigned long long u64;

// hidden state ping-pong, layout [b][t][ch]
__device__ float g_h0[(size_t)BB * TT * W];
__device__ float g_h1[(size_t)BB * TT * W];

__device__ __forceinline__ u64 pk2(float x){ u64 r; asm("mov.b64 %0,{%1,%1};":"=l"(r):"f"(x)); return r; }
__device__ __forceinline__ u64 pk(float lo, float hi){ u64 r; asm("mov.b64 %0,{%1,%2};":"=l"(r):"f"(lo),"f"(hi)); return r; }
__device__ __forceinline__ void unpk(u64 v, float& lo, float& hi){ asm("mov.b64 {%0,%1},%2;":"=f"(lo),"=f"(hi):"l"(v)); }
__device__ __forceinline__ u64 fma2(u64 a, u64 b, u64 c){ u64 d; asm("fma.rn.f32x2 %0,%1,%2,%3;":"=l"(d):"l"(a),"l"(b),"l"(c)); return d; }
__device__ __forceinline__ u64 mul2(u64 a, u64 b){ u64 d; asm("mul.rn.f32x2 %0,%1,%2;":"=l"(d):"l"(a),"l"(b)); return d; }
__device__ __forceinline__ u64 add2(u64 a, u64 b){ u64 d; asm("add.rn.f32x2 %0,%1,%2;":"=l"(d):"l"(a),"l"(b)); return d; }
__device__ __forceinline__ float rcpf(float x){ float r; asm("rcp.approx.f32 %0,%1;":"=f"(r):"f"(x)); return r; }

#define ABS2 0x7FFFFFFF7FFFFFFFull
#define ONE2 0x3F8000003F800000ull

__device__ __forceinline__ u64 ssz(u64 f, u64 g){
    u64 df = add2(f & ABS2, ONE2);
    u64 dg = add2(g & ABS2, ONE2);
    u64 dd = mul2(df, dg);
    float dl, dh; unpk(dd, dl, dh);
    u64 rr = pk(rcpf(dl), rcpf(dh));
    return mul2(mul2(f, g), rr);
}

__global__ void start_kernel(const float* __restrict__ x,
                             const float* __restrict__ sw,
                             float* __restrict__ out) {
    int idx = blockIdx.x * blockDim.x + threadIdx.x;
    if (idx < BB * TT) {
        float xv = x[idx];
        #pragma unroll
        for (int o = 0; o < W; o++) g_h0[(size_t)idx * W + o] = sw[o] * xv;
        out[idx] = 0.f;
    }
}

// Row stride padded: R % 8 == 2 (conflict-free transpose store + residual reads)
__host__ __device__ __forceinline__ int padR(int d) {
    int R = TILE + 2 * d;
    R += ((2 - (R & 7)) + 8) & 7;
    return R;
}

// smem (floats):
//  [0:1536)     conv+gate weights: ((k*16+i)*2+cg)*16 + half*8 + j ; o=8cg+j; half0=f,1=g
//  [1536:1792)  res weights: (i*2+cg)*8 + j  = rw[o=8cg+j][i]
//  [1792:1808)  mixer  [1808:1824) conv bias [1824:1840) gate bias [1840:1856) res bias
//  [1856:...)   hT[ch][R] channel-major tile
__global__ __launch_bounds__(NTH, 2)
void layer8_kernel(const float* __restrict__ cw, const float* __restrict__ cb,
                   const float* __restrict__ gw, const float* __restrict__ gb,
                   const float* __restrict__ rw, const float* __restrict__ rb,
                   const float* __restrict__ mix, float* __restrict__ out,
                   int li, int d, int last)
{
    extern __shared__ float sh[];
    const float* hin  = (li & 1) ? g_h1 : g_h0;
    float*       hout = (li & 1) ? g_h0 : g_h1;
    const int b   = blockIdx.y;
    const int t0  = blockIdx.x * TILE;
    const int tid = threadIdx.x;
    const int R   = padR(d);
    float* hT = sh + HOFF;

    // ---- weight prep ----
    for (int w = tid; w < 1536; w += NTH) {
        int k = w >> 9, rem = w & 511;
        int pair = rem >> 4, w16 = rem & 15;
        int i = pair >> 1, cgx = pair & 1;
        int half = w16 >> 3, j = w16 & 7;
        const float* src = half ? gw : cw;
        sh[w] = src[li * 768 + (8 * cgx + j) * 48 + i * 3 + k];
    }
    for (int w = tid; w < 256; w += NTH) {
        int i = w >> 4, rem = w & 15;
        int cgx = rem >> 3, j = rem & 7;
        sh[1536 + w] = last ? 0.f : rw[li * 256 + (8 * cgx + j) * 16 + i];
    }
    if (tid < 16) {
        sh[1792 + tid] = mix[li * 16 + tid];
        sh[1808 + tid] = cb[li * 16 + tid];
        sh[1824 + tid] = gb[li * 16 + tid];
        sh[1840 + tid] = last ? 0.f : rb[li * 16 + tid];
    }

    // ---- h tile load, transposing [t][ch] -> [ch][t] ----
    {
        const int n4 = (TILE + 2 * d) * 4;
        for (int idx = tid; idx < n4; idx += NTH) {
            int r = idx >> 2, c = idx & 3;
            int gt = t0 - 2 * d + r;
            float4 v = make_float4(0.f, 0.f, 0.f, 0.f);
            if (gt >= 0)
                v = *(const float4*)(hin + ((size_t)b * TT + gt) * W + 4 * c);
            hT[(4 * c + 0) * R + r] = v.x;
            hT[(4 * c + 1) * R + r] = v.y;
            hT[(4 * c + 2) * R + r] = v.z;
            hT[(4 * c + 3) * R + r] = v.w;
        }
    }
    __syncthreads();

    // ---- lane mapping: 16 ts-lanes x 2 channel-groups; 4 slots of 16 ts ----
    const int lane = tid & 31;
    const int warp = tid >> 5;
    const int ct   = lane & 15;
    const int cg   = lane >> 4;          // 0: ch 0-7, 1: ch 8-15
    const int tb   = warp * 64 + ct;     // local ts of slot 0

    // ---- conv: f[s][jp], g[s][jp] cover channels (8cg+2jp, 8cg+2jp+1) ----
    u64 f[4][4], g[4][4];
    {
        const u64* cbp = (const u64*)(sh + 1808) + cg * 4;
        const u64* gbp = (const u64*)(sh + 1824) + cg * 4;
        #pragma unroll
        for (int jp = 0; jp < 4; jp++) {
            u64 cv = cbp[jp], gv = gbp[jp];
            #pragma unroll
            for (int s = 0; s < 4; s++) { f[s][jp] = cv; g[s][jp] = gv; }
        }
    }

    #pragma unroll 1
    for (int k = 0; k < 3; k++) {
        const float* tp = hT + tb + k * d;
        #pragma unroll 4
        for (int i = 0; i < 16; i++) {
            const float* row = tp + i * R;
            u64 hp0 = pk2(row[0]);
            u64 hp1 = pk2(row[16]);
            u64 hp2 = pk2(row[32]);
            u64 hp3 = pk2(row[48]);
            const ulonglong2* wp =
                (const ulonglong2*)sh + ((k * 16 + i) * 2 + cg) * 4;
            ulonglong2 wf0 = wp[0], wf1 = wp[1];   // f: ch pairs 0-3 of group
            ulonglong2 wg0 = wp[2], wg1 = wp[3];   // g
            f[0][0] = fma2(wf0.x, hp0, f[0][0]);
            f[0][1] = fma2(wf0.y, hp0, f[0][1]);
            f[0][2] = fma2(wf1.x, hp0, f[0][2]);
            f[0][3] = fma2(wf1.y, hp0, f[0][3]);
            g[0][0] = fma2(wg0.x, hp0, g[0][0]);
            g[0][1] = fma2(wg0.y, hp0, g[0][1]);
            g[0][2] = fma2(wg1.x, hp0, g[0][2]);
            g[0][3] = fma2(wg1.y, hp0, g[0][3]);
            f[1][0] = fma2(wf0.x, hp1, f[1][0]);
            f[1][1] = fma2(wf0.y, hp1, f[1][1]);
            f[1][2] = fma2(wf1.x, hp1, f[1][2]);
            f[1][3] = fma2(wf1.y, hp1, f[1][3]);
            g[1][0] = fma2(wg0.x, hp1, g[1][0]);
            g[1][1] = fma2(wg0.y, hp1, g[1][1]);
            g[1][2] = fma2(wg1.x, hp1, g[1][2]);
            g[1][3] = fma2(wg1.y, hp1, g[1][3]);
            f[2][0] = fma2(wf0.x, hp2, f[2][0]);
            f[2][1] = fma2(wf0.y, hp2, f[2][1]);
            f[2][2] = fma2(wf1.x, hp2, f[2][2]);
            f[2][3] = fma2(wf1.y, hp2, f[2][3]);
            g[2][0] = fma2(wg0.x, hp2, g[2][0]);
            g[2][1] = fma2(wg0.y, hp2, g[2][1]);
            g[2][2] = fma2(wg1.x, hp2, g[2][2]);
            g[2][3] = fma2(wg1.y, hp2, g[2][3]);
            f[3][0] = fma2(wf0.x, hp3, f[3][0]);
            f[3][1] = fma2(wf0.y, hp3, f[3][1]);
            f[3][2] = fma2(wf1.x, hp3, f[3][2]);
            f[3][3] = fma2(wf1.y, hp3, f[3][3]);
            g[3][0] = fma2(wg0.x, hp3, g[3][0]);
            g[3][1] = fma2(wg0.y, hp3, g[3][1]);
            g[3][2] = fma2(wg1.x, hp3, g[3][2]);
            g[3][3] = fma2(wg1.y, hp3, g[3][3]);
        }
    }

    // ---- epilogue: two phases of 2 slots each (caps live registers) ----
    const u64* mp  = (const u64*)(sh + 1792);
    const u64* rbp = (const u64*)(sh + 1840) + cg * 4;

    #pragma unroll
    for (int ph = 0; ph < 2; ph++) {
        float zf[2][16];                 // full z, unpacked, per slot in phase
        #pragma unroll
        for (int sl = 0; sl < 2; sl++) {
            const int s = 2 * ph + sl;
            u64 z[4], zo[4];
            #pragma unroll
            for (int jp = 0; jp < 4; jp++) {
                z[jp]  = ssz(f[s][jp], g[s][jp]);
                zo[jp] = __shfl_xor_sync(0xFFFFFFFFu, z[jp], 16);
            }
            // zl = ch0-7 pairs, zh = ch8-15 pairs
            u64 zl[4], zh[4];
            #pragma unroll
            for (int jp = 0; jp < 4; jp++) {
                zl[jp] = cg ? zo[jp] : z[jp];
                zh[jp] = cg ? z[jp]  : zo[jp];
            }
            // mixer
            u64 acc = mul2(mp[0], zl[0]);
            acc = fma2(mp[1], zl[1], acc);
            acc = fma2(mp[2], zl[2], acc);
            acc = fma2(mp[3], zl[3], acc);
            acc = fma2(mp[4], zh[0], acc);
            acc = fma2(mp[5], zh[1], acc);
            acc = fma2(mp[6], zh[2], acc);
            acc = fma2(mp[7], zh[3], acc);
            float a, c; unpk(acc, a, c);
            if (cg == 0)
                out[(size_t)b * TT + t0 + tb + 16 * s] += a + c;
            // unpack z to floats for residual
            #pragma unroll
            for (int jp = 0; jp < 4; jp++) {
                unpk(zl[jp], zf[sl][2*jp],     zf[sl][2*jp + 1]);
                unpk(zh[jp], zf[sl][8 + 2*jp], zf[sl][9 + 2*jp]);
            }
        }

        if (!last) {
            u64 hn[2][4];
            #pragma unroll
            for (int sl = 0; sl < 2; sl++) {
                const int rr = 2 * d + tb + 16 * (2 * ph + sl);
                #pragma unroll
                for (int jp = 0; jp < 4; jp++) {
                    float a = hT[(8 * cg + 2 * jp)     * R + rr];
                    float c = hT[(8 * cg + 2 * jp + 1) * R + rr];
                    hn[sl][jp] = add2(pk(a, c), rbp[jp]);
                }
            }
            #pragma unroll 4
            for (int i = 0; i < 16; i++) {
                const ulonglong2* rp =
                    (const ulonglong2*)(sh + 1536) + (i * 2 + cg) * 2;
                ulonglong2 r01 = rp[0], r23 = rp[1];
                #pragma unroll
                for (int sl = 0; sl < 2; sl++) {
                    u64 zi = pk2(zf[sl][i]);
                    hn[sl][0] = fma2(r01.x, zi, hn[sl][0]);
                    hn[sl][1] = fma2(r01.y, zi, hn[sl][1]);
                    hn[sl][2] = fma2(r23.x, zi, hn[sl][2]);
                    hn[sl][3] = fma2(r23.y, zi, hn[sl][3]);
                }
            }
            #pragma unroll
            for (int sl = 0; sl < 2; sl++) {
                const int s = 2 * ph + sl;
                ulonglong2* o = (ulonglong2*)(hout +
                    ((size_t)b * TT + t0 + tb + 16 * s) * W + 8 * cg);
                o[0] = make_ulonglong2(hn[sl][0], hn[sl][1]);
                o[1] = make_ulonglong2(hn[sl][2], hn[sl][3]);
            }
        }
    }
}

extern "C" void kernel_launch(void* const* d_in, const int* in_sizes, int n_in,
                              void* d_out, int out_size) {
    const float* x   = (const float*)d_in[0];
    const float* sw  = (const float*)d_in[1];
    const float* cw  = (const float*)d_in[2];
    const float* cb  = (const float*)d_in[3];
    const float* gw  = (const float*)d_in[4];
    const float* gb  = (const float*)d_in[5];
    const float* rw  = (const float*)d_in[6];
    const float* rb  = (const float*)d_in[7];
    const float* mix = (const float*)d_in[8];
    float* out = (float*)d_out;

    static const int dil[NL] = {1,2,4,8,16,32,64,128,256,
                                1,2,4,8,16,32,64,128,256};

    const int max_smem = (HOFF + W * padR(256)) * (int)sizeof(float);
    cudaFuncSetAttribute(layer8_kernel,
                         cudaFuncAttributeMaxDynamicSharedMemorySize, max_smem);

    start_kernel<<<(BB * TT + 255) / 256, 256>>>(x, sw, out);

    dim3 grid(TT / TILE, BB);
    for (int li = 0; li < NL; li++) {
        int d = dil[li];
        int smem = (HOFF + W * padR(d)) * (int)sizeof(float);
        layer8_kernel<<<grid, NTH, smem>>>(
            cw, cb, gw, gb, rw, rb, mix, out,
            li, d, (li == NL - 1) ? 1 : 0);
    }
}

// round 10
// speedup vs baseline: 2.0184x; 2.0184x over previous
#include <cuda_runtime.h>
#include <cuda_bf16.h>

#define TT    65536
#define BB    4
#define W     16
#define NL    18
#define TILEC 256          // ts per CTA (4 warps x 64)
#define NTH   128
#define ZR    72           // zbuf row stride (mod 32 == 8)
#define TFMASK 0xFFFFE000u

typedef unsigned long long u64;
typedef unsigned int u32;

__device__ float g_h0[(size_t)BB * TT * W];   // [b][t][ch]
__device__ float g_h1[(size_t)BB * TT * W];

__device__ __forceinline__ u64 pk(float lo, float hi){ u64 r; asm("mov.b64 %0,{%1,%2};":"=l"(r):"f"(lo),"f"(hi)); return r; }
__device__ __forceinline__ void unpk(u64 v, float& lo, float& hi){ asm("mov.b64 {%0,%1},%2;":"=f"(lo),"=f"(hi):"l"(v)); }
__device__ __forceinline__ u64 mul2(u64 a, u64 b){ u64 d; asm("mul.rn.f32x2 %0,%1,%2;":"=l"(d):"l"(a),"l"(b)); return d; }
__device__ __forceinline__ u64 add2(u64 a, u64 b){ u64 d; asm("add.rn.f32x2 %0,%1,%2;":"=l"(d):"l"(a),"l"(b)); return d; }
__device__ __forceinline__ float rcpf(float x){ float r; asm("rcp.approx.f32 %0,%1;":"=f"(r):"f"(x)); return r; }

#define ABS2 0x7FFFFFFF7FFFFFFFull
#define ONE2 0x3F8000003F800000ull

// z = softsign(f)*softsign(g), packed over 2 values
__device__ __forceinline__ u64 ssz(u64 f, u64 g){
    u64 df = add2(f & ABS2, ONE2);
    u64 dg = add2(g & ABS2, ONE2);
    u64 dd = mul2(df, dg);
    float dl, dh; unpk(dd, dl, dh);
    u64 rr = pk(rcpf(dl), rcpf(dh));
    return mul2(mul2(f, g), rr);
}

// m16n8k8 tf32 mma, row.col, fp32 accumulate (in place)
__device__ __forceinline__ void mma8(float* d, const u32* a, u32 b0, u32 b1){
    asm volatile(
        "mma.sync.aligned.m16n8k8.row.col.f32.tf32.tf32.f32 "
        "{%0,%1,%2,%3}, {%4,%5,%6,%7}, {%8,%9}, {%0,%1,%2,%3};"
        : "+f"(d[0]), "+f"(d[1]), "+f"(d[2]), "+f"(d[3])
        : "r"(a[0]), "r"(a[1]), "r"(a[2]), "r"(a[3]), "r"(b0), "r"(b1));
}

__device__ __forceinline__ void tfsplit(float x, u32& hi, u32& lo){
    u32 xb = __float_as_uint(x) & TFMASK;
    hi = xb;
    lo = __float_as_uint(x - __uint_as_float(xb));
}

__global__ void start_kernel(const float* __restrict__ x,
                             const float* __restrict__ sw,
                             float* __restrict__ out) {
    int idx = blockIdx.x * blockDim.x + threadIdx.x;
    if (idx < BB * TT) {
        float xv = x[idx];
        #pragma unroll
        for (int o = 0; o < W; o++) g_h0[(size_t)idx * W + o] = sw[o] * xv;
        out[idx] = 0.f;
    }
}

__host__ __device__ __forceinline__ int padRt(int d) {
    int R = TILEC + 2 * d;
    R += ((8 - (R & 31)) + 32) & 31;   // R % 32 == 8
    return R;
}

// smem (floats):
//  [0:4608)      conv A: [blk2(f,g)][chunk6][hl2][row16 x stride12]  (cols 0..7 used)
//  [4608:6144)   res  A: [blk2(R,M)][chunk2][hl2][row16 x stride12]
//  [6144:6160) cb  [6160:6176) gb  [6176:6192) rb   [6192:6208) pad
//  [6208:6208+16*Rt)  hT[ch][Rt] channel-major tile (fp32)
//  [+ :  +4*16*ZR)    zbuf, per-warp 16 x ZR
__global__ __launch_bounds__(NTH, 2)
void layer9_kernel(const float* __restrict__ cw, const float* __restrict__ cb,
                   const float* __restrict__ gw, const float* __restrict__ gb,
                   const float* __restrict__ rw, const float* __restrict__ rb,
                   const float* __restrict__ mix, float* __restrict__ out,
                   int li, int d, int last)
{
    extern __shared__ float sh[];
    const float* hin  = (li & 1) ? g_h1 : g_h0;
    float*       hout = (li & 1) ? g_h0 : g_h1;
    const int b   = blockIdx.y;
    const int t0  = blockIdx.x * TILEC;
    const int tid = threadIdx.x;
    const int Rt  = padRt(d);
    float* hT = sh + 6208;

    // ---- conv/gate weight prep: hi/lo tf32 split ----
    for (int idx = tid; idx < 1536; idx += NTH) {
        int blk = idx / 768, rem = idx % 768;
        int c = rem >> 7, rr = rem & 127;
        int o = rr >> 3, kk = rr & 7;
        int i = (c & 1) * 8 + kk, kt = c >> 1;
        float wv = (blk ? gw : cw)[li * 768 + o * 48 + i * 3 + kt];
        u32 hb = __float_as_uint(wv) & TFMASK;
        float hi = __uint_as_float(hb);
        int base = ((blk * 6 + c) * 2) * 192 + o * 12 + kk;
        sh[base]       = hi;
        sh[base + 192] = wv - hi;
    }
    // ---- residual (blk0) + mixer (blk1) A prep ----
    for (int idx = tid; idx < 512; idx += NTH) {
        int blk = idx / 256, rem = idx % 256;
        int rc = rem >> 7, rr = rem & 127;
        int o = rr >> 3, kk = rr & 7;
        int i = rc * 8 + kk;
        float v = 0.f;
        if (blk == 0) { if (!last) v = rw[li * 256 + o * 16 + i]; }
        else          { if (o == 0) v = mix[li * 16 + i]; }
        u32 hb = __float_as_uint(v) & TFMASK;
        float hi = __uint_as_float(hb);
        int base = 4608 + ((blk * 2 + rc) * 2) * 192 + o * 12 + kk;
        sh[base]       = hi;
        sh[base + 192] = v - hi;
    }
    if (tid < 16) {
        sh[6144 + tid] = cb[li * 16 + tid];
        sh[6160 + tid] = gb[li * 16 + tid];
        sh[6176 + tid] = last ? 0.f : rb[li * 16 + tid];
    }

    // ---- hT tile load: lane owns ROW r, stores 16 channels (conflict-free) ----
    {
        const int nrows = TILEC + 2 * d;
        for (int r = tid; r < nrows; r += NTH) {
            int gt = t0 - 2 * d + r;
            float4 v0, v1, v2, v3;
            if (gt >= 0) {
                const float4* s = (const float4*)(hin + ((size_t)b * TT + gt) * W);
                v0 = s[0]; v1 = s[1]; v2 = s[2]; v3 = s[3];
            } else {
                v0 = v1 = v2 = v3 = make_float4(0.f, 0.f, 0.f, 0.f);
            }
            hT[ 0 * Rt + r] = v0.x; hT[ 1 * Rt + r] = v0.y;
            hT[ 2 * Rt + r] = v0.z; hT[ 3 * Rt + r] = v0.w;
            hT[ 4 * Rt + r] = v1.x; hT[ 5 * Rt + r] = v1.y;
            hT[ 6 * Rt + r] = v1.z; hT[ 7 * Rt + r] = v1.w;
            hT[ 8 * Rt + r] = v2.x; hT[ 9 * Rt + r] = v2.y;
            hT[10 * Rt + r] = v2.z; hT[11 * Rt + r] = v2.w;
            hT[12 * Rt + r] = v3.x; hT[13 * Rt + r] = v3.y;
            hT[14 * Rt + r] = v3.z; hT[15 * Rt + r] = v3.w;
        }
    }
    __syncthreads();

    // ---- per-warp 64-ts tile ----
    const int lane = tid & 31;
    const int wid  = tid >> 5;
    const int gID  = lane >> 2;       // 0..7
    const int c4   = lane & 3;        // 0..3
    const int tloc = 2 * d + wid * 64;          // local row of warp ts0
    const int tw   = t0 + wid * 64;             // global ts0
    float* zw = sh + 6208 + 16 * Rt + wid * (16 * ZR);

    // ---- conv+gate GEMM: D = [Wf;Wg](32x48) x H48(48x64), 3xTF32 ----
    float Df[8][4], Dg[8][4];
    {
        float cbl = sh[6144 + gID], cbh = sh[6144 + 8 + gID];
        float gbl = sh[6160 + gID], gbh = sh[6160 + 8 + gID];
        #pragma unroll
        for (int tsb = 0; tsb < 8; tsb++) {
            Df[tsb][0] = cbl; Df[tsb][1] = cbl; Df[tsb][2] = cbh; Df[tsb][3] = cbh;
            Dg[tsb][0] = gbl; Dg[tsb][1] = gbl; Dg[tsb][2] = gbh; Dg[tsb][3] = gbh;
        }
    }

    #pragma unroll
    for (int c = 0; c < 6; c++) {
        const int kt = c >> 1, iB = (c & 1) * 8;
        const float* afh = sh + ((0 * 6 + c) * 2) * 192;
        const float* afl = afh + 192;
        const float* agh = sh + ((1 * 6 + c) * 2) * 192;
        const float* agl = agh + 192;
        u32 AF_h[4], AF_l[4], AG_h[4], AG_l[4];
        AF_h[0] = __float_as_uint(afh[gID * 12 + c4]);
        AF_h[1] = __float_as_uint(afh[(gID + 8) * 12 + c4]);
        AF_h[2] = __float_as_uint(afh[gID * 12 + c4 + 4]);
        AF_h[3] = __float_as_uint(afh[(gID + 8) * 12 + c4 + 4]);
        AF_l[0] = __float_as_uint(afl[gID * 12 + c4]);
        AF_l[1] = __float_as_uint(afl[(gID + 8) * 12 + c4]);
        AF_l[2] = __float_as_uint(afl[gID * 12 + c4 + 4]);
        AF_l[3] = __float_as_uint(afl[(gID + 8) * 12 + c4 + 4]);
        AG_h[0] = __float_as_uint(agh[gID * 12 + c4]);
        AG_h[1] = __float_as_uint(agh[(gID + 8) * 12 + c4]);
        AG_h[2] = __float_as_uint(agh[gID * 12 + c4 + 4]);
        AG_h[3] = __float_as_uint(agh[(gID + 8) * 12 + c4 + 4]);
        AG_l[0] = __float_as_uint(agl[gID * 12 + c4]);
        AG_l[1] = __float_as_uint(agl[(gID + 8) * 12 + c4]);
        AG_l[2] = __float_as_uint(agl[gID * 12 + c4 + 4]);
        AG_l[3] = __float_as_uint(agl[(gID + 8) * 12 + c4 + 4]);

        const int tb = tloc - (2 - kt) * d;     // >= 0 always
        #pragma unroll
        for (int tsb = 0; tsb < 8; tsb++) {
            float b0 = hT[(iB + c4)     * Rt + tb + tsb * 8 + gID];
            float b1 = hT[(iB + c4 + 4) * Rt + tb + tsb * 8 + gID];
            u32 b0h, b0l, b1h, b1l;
            tfsplit(b0, b0h, b0l);
            tfsplit(b1, b1h, b1l);
            mma8(Df[tsb], AF_h, b0h, b1h);
            mma8(Df[tsb], AF_h, b0l, b1l);
            mma8(Df[tsb], AF_l, b0h, b1h);
            mma8(Dg[tsb], AG_h, b0h, b1h);
            mma8(Dg[tsb], AG_h, b0l, b1l);
            mma8(Dg[tsb], AG_l, b0h, b1h);
        }
    }

    // ---- gated activation + z -> per-warp smem (zbuf[ch][t]) ----
    #pragma unroll
    for (int tsb = 0; tsb < 8; tsb++) {
        u64 z01 = ssz(pk(Df[tsb][0], Df[tsb][1]), pk(Dg[tsb][0], Dg[tsb][1]));
        u64 z23 = ssz(pk(Df[tsb][2], Df[tsb][3]), pk(Dg[tsb][2], Dg[tsb][3]));
        *(u64*)&zw[gID * ZR       + tsb * 8 + 2 * c4] = z01;
        *(u64*)&zw[(gID + 8) * ZR + tsb * 8 + 2 * c4] = z23;
    }
    __syncwarp();

    // ---- residual (blockR) + mixer (blockM) GEMM over z ----
    float Dr[8][4], Dm[8][4];
    if (!last) {
        float rbl = sh[6176 + gID], rbh = sh[6176 + 8 + gID];
        #pragma unroll
        for (int tsb = 0; tsb < 8; tsb++) {
            int t = tloc + tsb * 8 + 2 * c4;
            float h0, h1, h2, h3;
            { u64 v = *(const u64*)&hT[gID * Rt + t];       unpk(v, h0, h1); }
            { u64 v = *(const u64*)&hT[(gID + 8) * Rt + t]; unpk(v, h2, h3); }
            Dr[tsb][0] = h0 + rbl; Dr[tsb][1] = h1 + rbl;
            Dr[tsb][2] = h2 + rbh; Dr[tsb][3] = h3 + rbh;
        }
    }
    #pragma unroll
    for (int tsb = 0; tsb < 8; tsb++) {
        Dm[tsb][0] = 0.f; Dm[tsb][1] = 0.f; Dm[tsb][2] = 0.f; Dm[tsb][3] = 0.f;
    }

    #pragma unroll
    for (int rc = 0; rc < 2; rc++) {
        const float* arh = sh + 4608 + ((0 * 2 + rc) * 2) * 192;
        const float* arl = arh + 192;
        const float* amh = sh + 4608 + ((1 * 2 + rc) * 2) * 192;
        const float* aml = amh + 192;
        u32 AR_h[4], AR_l[4], AM_h[4], AM_l[4];
        AR_h[0] = __float_as_uint(arh[gID * 12 + c4]);
        AR_h[1] = __float_as_uint(arh[(gID + 8) * 12 + c4]);
        AR_h[2] = __float_as_uint(arh[gID * 12 + c4 + 4]);
        AR_h[3] = __float_as_uint(arh[(gID + 8) * 12 + c4 + 4]);
        AR_l[0] = __float_as_uint(arl[gID * 12 + c4]);
        AR_l[1] = __float_as_uint(arl[(gID + 8) * 12 + c4]);
        AR_l[2] = __float_as_uint(arl[gID * 12 + c4 + 4]);
        AR_l[3] = __float_as_uint(arl[(gID + 8) * 12 + c4 + 4]);
        AM_h[0] = __float_as_uint(amh[gID * 12 + c4]);
        AM_h[1] = __float_as_uint(amh[(gID + 8) * 12 + c4]);
        AM_h[2] = __float_as_uint(amh[gID * 12 + c4 + 4]);
        AM_h[3] = __float_as_uint(amh[(gID + 8) * 12 + c4 + 4]);
        AM_l[0] = __float_as_uint(aml[gID * 12 + c4]);
        AM_l[1] = __float_as_uint(aml[(gID + 8) * 12 + c4]);
        AM_l[2] = __float_as_uint(aml[gID * 12 + c4 + 4]);
        AM_l[3] = __float_as_uint(aml[(gID + 8) * 12 + c4 + 4]);

        #pragma unroll
        for (int tsb = 0; tsb < 8; tsb++) {
            float b0 = zw[(rc * 8 + c4)     * ZR + tsb * 8 + gID];
            float b1 = zw[(rc * 8 + c4 + 4) * ZR + tsb * 8 + gID];
            u32 b0h, b0l, b1h, b1l;
            tfsplit(b0, b0h, b0l);
            tfsplit(b1, b1h, b1l);
            if (!last) {
                mma8(Dr[tsb], AR_h, b0h, b1h);
                mma8(Dr[tsb], AR_h, b0l, b1l);
                mma8(Dr[tsb], AR_l, b0h, b1h);
            }
            mma8(Dm[tsb], AM_h, b0h, b1h);
            mma8(Dm[tsb], AM_h, b0l, b1l);
            mma8(Dm[tsb], AM_l, b0h, b1h);
        }
    }

    // ---- stores ----
    if (!last) {
        #pragma unroll
        for (int tsb = 0; tsb < 8; tsb++) {
            size_t base = ((size_t)b * TT + tw + tsb * 8 + 2 * c4) * W;
            hout[base + gID]          = Dr[tsb][0];
            hout[base + W + gID]      = Dr[tsb][1];
            hout[base + gID + 8]      = Dr[tsb][2];
            hout[base + W + gID + 8]  = Dr[tsb][3];
        }
    }
    if (gID == 0) {
        #pragma unroll
        for (int tsb = 0; tsb < 8; tsb++) {
            size_t o = (size_t)b * TT + tw + tsb * 8 + 2 * c4;
            out[o]     += Dm[tsb][0];
            out[o + 1] += Dm[tsb][1];
        }
    }
}

extern "C" void kernel_launch(void* const* d_in, const int* in_sizes, int n_in,
                              void* d_out, int out_size) {
    const float* x   = (const float*)d_in[0];
    const float* sw  = (const float*)d_in[1];
    const float* cw  = (const float*)d_in[2];
    const float* cb  = (const float*)d_in[3];
    const float* gw  = (const float*)d_in[4];
    const float* gb  = (const float*)d_in[5];
    const float* rw  = (const float*)d_in[6];
    const float* rb  = (const float*)d_in[7];
    const float* mix = (const float*)d_in[8];
    float* out = (float*)d_out;

    static const int dil[NL] = {1,2,4,8,16,32,64,128,256,
                                1,2,4,8,16,32,64,128,256};

    const int max_smem = (6208 + 16 * padRt(256) + 4 * 16 * ZR) * (int)sizeof(float);
    cudaFuncSetAttribute(layer9_kernel,
                         cudaFuncAttributeMaxDynamicSharedMemorySize, max_smem);

    start_kernel<<<(BB * TT + 255) / 256, 256>>>(x, sw, out);

    dim3 grid(TT / TILEC, BB);
    for (int li = 0; li < NL; li++) {
        int d = dil[li];
        int smem = (6208 + 16 * padRt(d) + 4 * 16 * ZR) * (int)sizeof(float);
        layer9_kernel<<<grid, NTH, smem>>>(
            cw, cb, gw, gb, rw, rb, mix, out,
            li, d, (li == NL - 1) ? 1 : 0);
    }
}